// round 2
// baseline (speedup 1.0000x reference)
#include <cuda_runtime.h>
#include <math.h>

#define BB 8
#define CC 64
#define HH 128
#define WW 128
#define HWD 16384
#define NS 3
#define K54 54
#define CNT 131072.0f
#define BN_EPS 1e-5f

// ---------------- scratch (device globals; no runtime allocation) ----------
__device__ float g_xT[BB * HWD * CC];          // x as [b][hw][c]      (33.5 MB)
__device__ float g_off[BB * HWD * K54];        // offsets channel-last (28.3 MB)
__device__ float g_Wt[CC * 9 * K54];           // Wp as [ci][tap][k54]
__device__ float g_y[NS * BB * CC * HWD];      // pre-BN y [s][b][o][hw] (100 MB)
__device__ float g_sum[NS * CC];
__device__ float g_sumsq[NS * CC];
__device__ float g_AB[NS * CC * 2];            // A = gamma*rsqrt(var+eps), B = beta-mu*A

// ---------------- k0: transpose x (b,c,hw) -> (b,hw,c) ---------------------
__global__ void k_transpose(const float* __restrict__ x) {
    __shared__ float t[32][33];
    int b = blockIdx.z;
    int hw0 = blockIdx.x * 32;
    int c0 = blockIdx.y * 32;
    int tx = threadIdx.x, ty = threadIdx.y;   // (32, 8)
#pragma unroll
    for (int j = 0; j < 4; j++)
        t[ty + 8 * j][tx] = x[(b * CC + c0 + ty + 8 * j) * HWD + hw0 + tx];
    __syncthreads();
#pragma unroll
    for (int j = 0; j < 4; j++)
        g_xT[(b * HWD + hw0 + ty + 8 * j) * CC + c0 + tx] = t[tx][ty + 8 * j];
}

// ---------------- k1: transpose Wp + zero stats -----------------------------
__global__ void k_prep(const float* __restrict__ Wp) {
    int idx = blockIdx.x * blockDim.x + threadIdx.x;
    if (idx < CC * 9 * K54) {
        int ci = idx / (9 * K54);
        int rem = idx % (9 * K54);
        int tap = rem / K54;
        int k = rem % K54;
        g_Wt[idx] = Wp[(k * CC + ci) * 9 + tap];
    }
    if (idx < NS * CC) { g_sum[idx] = 0.f; g_sumsq[idx] = 0.f; }
}

// ---------------- k2: 3x3 offset conv, 64 -> 54 ch --------------------------
// block = 128 threads = one output row; loops input channels through smem.
__global__ void __launch_bounds__(128) k_conv(const float* __restrict__ x,
                                              const float* __restrict__ bp) {
    __shared__ float xs[3 * 130];     // rows h-1..h+1, cols -1..128
    __shared__ float ws[9 * 56];      // [tap][k54], pitch 56 (16B aligned)
    int b = blockIdx.y;
    int h = blockIdx.x;
    int w = threadIdx.x;

    float acc[K54];
#pragma unroll
    for (int k = 0; k < K54; k++) acc[k] = 0.f;

    for (int ci = 0; ci < CC; ci++) {
        __syncthreads();
        const float* xc = x + (b * CC + ci) * HWD;
        for (int idx = w; idx < 3 * 130; idx += 128) {
            int r = idx / 130, cw = idx % 130 - 1;
            int hh = h - 1 + r;
            float v = 0.f;
            if (hh >= 0 && hh < HH && cw >= 0 && cw < WW) v = xc[hh * WW + cw];
            xs[r * 130 + cw + 1] = v;
        }
        for (int idx = w; idx < 9 * K54; idx += 128)
            ws[(idx / K54) * 56 + idx % K54] = g_Wt[ci * 9 * K54 + idx];
        __syncthreads();

        float xv[9];
#pragma unroll
        for (int dh = 0; dh < 3; dh++)
#pragma unroll
            for (int dw = 0; dw < 3; dw++)
                xv[dh * 3 + dw] = xs[dh * 130 + w + dw];
#pragma unroll
        for (int tap = 0; tap < 9; tap++) {
            float a = xv[tap];
            const float4* wr = (const float4*)&ws[tap * 56];
#pragma unroll
            for (int k4 = 0; k4 < 13; k4++) {
                float4 wv = wr[k4];
                int k = k4 * 4;
                acc[k + 0] = fmaf(a, wv.x, acc[k + 0]);
                acc[k + 1] = fmaf(a, wv.y, acc[k + 1]);
                acc[k + 2] = fmaf(a, wv.z, acc[k + 2]);
                acc[k + 3] = fmaf(a, wv.w, acc[k + 3]);
            }
            acc[52] = fmaf(a, ws[tap * 56 + 52], acc[52]);
            acc[53] = fmaf(a, ws[tap * 56 + 53], acc[53]);
        }
    }
    float* op = g_off + (b * HWD + h * WW + w) * K54;
#pragma unroll
    for (int k = 0; k < K54; k++) {
        float sc = (k < 18) ? 1.f : ((k < 36) ? 2.f : 3.f);
        op[k] = (acc[k] + bp[k]) * sc;
    }
}

// ---------------- k3: gather + bilinear + channel mix + stats ---------------
// block = 256 thr handles 64 pixels of one (s,b,h) row.
// Phase A: 16 lanes per pixel, lane = 4 channels (float4 gathers).
// Phase B: 64x64 GEMM; thread = (pixel, 16 outputs).
__global__ void __launch_bounds__(256) k_gather(const float* __restrict__ WcG) {
    __shared__ float Wc_sh[64 * 64];      // [c][o]
    __shared__ float xoff[64 * 65];       // [p][c] pitch 65

    int h = blockIdx.x >> 1;
    int w0 = (blockIdx.x & 1) * 64;
    int b = blockIdx.y, s = blockIdx.z;
    int tid = threadIdx.x;

    for (int idx = tid; idx < 4096; idx += 256) {
        int o = idx >> 6, c = idx & 63;
        Wc_sh[c * 64 + o] = WcG[s * 4096 + idx];   // Wc[o][c] -> [c][o]
    }

    int grp = tid >> 4, l = tid & 15;
    const float* xTb = g_xT + b * HWD * CC;
    const float inv9 = 1.f / 9.f;
#pragma unroll
    for (int iter = 0; iter < 4; iter++) {
        int p = iter * 16 + grp;
        const float* offp = g_off + ((b * HWD + h * WW + w0 + p) * K54 + s * 18);
        int raw = 0; float fx = 0.f, fy = 0.f;
        if (l < 9) {
            float px = (float)(h + l / 3) + offp[l];
            float py = (float)(w0 + p + l % 3) + offp[9 + l];
            float flx = floorf(px), fly = floorf(py);
            fx = px - flx; fy = py - fly;
            raw = (int)(flx * 128.f + fly);
        }
        float a0 = 0.f, a1 = 0.f, a2 = 0.f, a3 = 0.f;
#pragma unroll
        for (int n = 0; n < 9; n++) {
            int r = __shfl_sync(0xffffffffu, raw, n, 16);
            float fxn = __shfl_sync(0xffffffffu, fx, n, 16);
            float fyn = __shfl_sync(0xffffffffu, fy, n, 16);
            float wlt = (1.f - fxn) * (1.f - fyn);
            float wrb = fxn * fyn;
            float wlb = (1.f - fxn) * fyn;       // corner (ltx, rby) -> +1
            float wrt = fxn * (1.f - fyn);       // corner (rbx, lty) -> +128
            int ilt = min(max(r, 0), HWD - 1);
            int ilb = min(max(r + 1, 0), HWD - 1);
            int irt = min(max(r + 128, 0), HWD - 1);
            int irb = min(max(r + 129, 0), HWD - 1);
            float4 v;
            v = *(const float4*)(xTb + ilt * CC + l * 4);
            a0 = fmaf(wlt, v.x, a0); a1 = fmaf(wlt, v.y, a1);
            a2 = fmaf(wlt, v.z, a2); a3 = fmaf(wlt, v.w, a3);
            v = *(const float4*)(xTb + irb * CC + l * 4);
            a0 = fmaf(wrb, v.x, a0); a1 = fmaf(wrb, v.y, a1);
            a2 = fmaf(wrb, v.z, a2); a3 = fmaf(wrb, v.w, a3);
            v = *(const float4*)(xTb + ilb * CC + l * 4);
            a0 = fmaf(wlb, v.x, a0); a1 = fmaf(wlb, v.y, a1);
            a2 = fmaf(wlb, v.z, a2); a3 = fmaf(wlb, v.w, a3);
            v = *(const float4*)(xTb + irt * CC + l * 4);
            a0 = fmaf(wrt, v.x, a0); a1 = fmaf(wrt, v.y, a1);
            a2 = fmaf(wrt, v.z, a2); a3 = fmaf(wrt, v.w, a3);
        }
        xoff[p * 65 + l * 4 + 0] = a0 * inv9;
        xoff[p * 65 + l * 4 + 1] = a1 * inv9;
        xoff[p * 65 + l * 4 + 2] = a2 * inv9;
        xoff[p * 65 + l * 4 + 3] = a3 * inv9;
    }
    __syncthreads();

    // Phase B: y[p][o] = sum_c xoff[p][c] * Wc[o][c]
    int p = tid & 63;
    int obase = (tid >> 6) * 16;
    float acc[16];
#pragma unroll
    for (int q = 0; q < 16; q++) acc[q] = 0.f;
    for (int c = 0; c < 64; c++) {
        float xv = xoff[p * 65 + c];
        const float4* w4 = (const float4*)&Wc_sh[c * 64 + obase];
#pragma unroll
        for (int j = 0; j < 4; j++) {
            float4 wv = w4[j];
            acc[4 * j + 0] = fmaf(xv, wv.x, acc[4 * j + 0]);
            acc[4 * j + 1] = fmaf(xv, wv.y, acc[4 * j + 1]);
            acc[4 * j + 2] = fmaf(xv, wv.z, acc[4 * j + 2]);
            acc[4 * j + 3] = fmaf(xv, wv.w, acc[4 * j + 3]);
        }
    }
    float* yb = g_y + ((size_t)(s * BB + b) * CC) * HWD + h * WW + w0;
#pragma unroll
    for (int q = 0; q < 16; q++) yb[(obase + q) * HWD + p] = acc[q];

    // BN partial stats: warp-reduce each output channel over this warp's 32 pixels
    int lane = tid & 31;
#pragma unroll
    for (int q = 0; q < 16; q++) {
        float v = acc[q], v2 = v * v;
#pragma unroll
        for (int ofs = 16; ofs > 0; ofs >>= 1) {
            v += __shfl_down_sync(0xffffffffu, v, ofs);
            v2 += __shfl_down_sync(0xffffffffu, v2, ofs);
        }
        if (lane == 0) {
            atomicAdd(&g_sum[s * CC + obase + q], v);
            atomicAdd(&g_sumsq[s * CC + obase + q], v2);
        }
    }
}

// ---------------- k4: finalize BN coefficients ------------------------------
__global__ void k_stats(const float* __restrict__ gamma, const float* __restrict__ beta) {
    int t = threadIdx.x;
    if (t < NS * CC) {
        float inv = 1.f / CNT;
        float mu = g_sum[t] * inv;
        float var = g_sumsq[t] * inv - mu * mu;
        float A = gamma[t] * rsqrtf(var + BN_EPS);
        g_AB[t * 2] = A;
        g_AB[t * 2 + 1] = beta[t] - mu * A;
    }
}

// ---------------- k5: normalize + SiLU + average scales ---------------------
__global__ void k_final(float* __restrict__ out) {
    int idx = blockIdx.x * blockDim.x + threadIdx.x;   // over B*C*HWD
    int o = (idx >> 14) & 63;
    float r = 0.f;
#pragma unroll
    for (int s = 0; s < NS; s++) {
        float v = g_y[(size_t)s * BB * CC * HWD + idx];
        int t = s * CC + o;
        float yn = fmaf(v, g_AB[t * 2], g_AB[t * 2 + 1]);
        r += yn / (1.f + expf(-yn));
    }
    out[idx] = r * (1.f / 3.f);
}

// ---------------- launch ----------------------------------------------------
extern "C" void kernel_launch(void* const* d_in, const int* in_sizes, int n_in,
                              void* d_out, int out_size) {
    const float* x     = (const float*)d_in[0];
    const float* Wp    = (const float*)d_in[1];
    const float* bp    = (const float*)d_in[2];
    const float* Wc    = (const float*)d_in[3];
    const float* gamma = (const float*)d_in[4];
    const float* beta  = (const float*)d_in[5];
    float* out = (float*)d_out;

    dim3 tb(32, 8);
    dim3 tg(HWD / 32, CC / 32, BB);
    k_transpose<<<tg, tb>>>(x);
    k_prep<<<128, 256>>>(Wp);
    k_conv<<<dim3(HH, BB), 128>>>(x, bp);
    k_gather<<<dim3(HH * 2, BB, NS), 256>>>(Wc);
    k_stats<<<1, 256>>>(gamma, beta);
    k_final<<<(BB * CC * HWD) / 256, 256>>>(out);
}

// round 4
// speedup vs baseline: 1.0650x; 1.0650x over previous
#include <cuda_runtime.h>
#include <cuda_fp16.h>
#include <math.h>

#define BB 8
#define CC 64
#define HH 128
#define WW 128
#define HWD 16384
#define NS 3
#define K54 54
#define CNT 131072.0f
#define BN_EPS 1e-5f

// ---------------- scratch (device globals; no runtime allocation) ----------
__device__ __half g_xH[BB * HWD * CC];         // x as [b][hw][c] fp16 (16.8 MB)
__device__ float g_off[BB * HWD * K54];        // offsets channel-last (28.3 MB)
__device__ float g_Wt[CC * 9 * K54];           // Wp as [ci][tap][k54]
__device__ float g_y[NS * BB * CC * HWD];      // pre-BN y [s][b][o][hw] (100 MB)
__device__ float g_sum[NS * CC];
__device__ float g_sumsq[NS * CC];
__device__ float g_AB[NS * CC * 2];            // A = gamma*rsqrt(var+eps), B = beta-mu*A

// ---------------- k0: transpose x (b,c,hw) -> (b,hw,c) fp16 ----------------
__global__ void k_transpose(const float* __restrict__ x) {
    __shared__ float t[32][33];                // t[c_local][hw_local]
    int b = blockIdx.z;
    int hw0 = blockIdx.x * 32;
    int c0 = blockIdx.y * 32;
    int tx = threadIdx.x, ty = threadIdx.y;   // (32, 8)
    int tid = ty * 32 + tx;
#pragma unroll
    for (int j = 0; j < 4; j++)
        t[ty + 8 * j][tx] = x[(b * CC + c0 + ty + 8 * j) * HWD + hw0 + tx];
    __syncthreads();
    // write half2 pairs: 32 hw rows x 16 channel-pairs  (FIX: t is [c][hw])
    __half2* outp = (__half2*)g_xH;
#pragma unroll
    for (int idx = tid; idx < 512; idx += 256) {
        int hwl = idx >> 4, cp = idx & 15;
        __half2 v = __floats2half2_rn(t[2 * cp][hwl], t[2 * cp + 1][hwl]);
        outp[((size_t)(b * HWD + hw0 + hwl) * CC + c0) / 2 + cp] = v;
    }
}

// ---------------- k1: transpose Wp + zero stats -----------------------------
__global__ void k_prep(const float* __restrict__ Wp) {
    int idx = blockIdx.x * blockDim.x + threadIdx.x;
    if (idx < CC * 9 * K54) {
        int ci = idx / (9 * K54);
        int rem = idx % (9 * K54);
        int tap = rem / K54;
        int k = rem % K54;
        g_Wt[idx] = Wp[(k * CC + ci) * 9 + tap];
    }
    if (idx < NS * CC) { g_sum[idx] = 0.f; g_sumsq[idx] = 0.f; }
}

// ---------------- k2: 3x3 offset conv, 64 -> 54 ch, 2 rows per thread ------
__global__ void __launch_bounds__(128) k_conv(const float* __restrict__ x,
                                              const float* __restrict__ bp) {
    __shared__ float xs[4 * 130];     // rows h0-1..h0+2, cols -1..128
    __shared__ float ws[9 * 56];      // [tap][k54], pitch 56 (16B aligned)
    int b = blockIdx.y;
    int h0 = blockIdx.x * 2;
    int w = threadIdx.x;

    float acc0[K54], acc1[K54];
#pragma unroll
    for (int k = 0; k < K54; k++) { acc0[k] = 0.f; acc1[k] = 0.f; }

    for (int ci = 0; ci < CC; ci++) {
        __syncthreads();
        const float* xc = x + (b * CC + ci) * HWD;
        for (int idx = w; idx < 4 * 130; idx += 128) {
            int r = idx / 130, cw = idx % 130 - 1;
            int hh = h0 - 1 + r;
            float v = 0.f;
            if (hh >= 0 && hh < HH && cw >= 0 && cw < WW) v = xc[hh * WW + cw];
            xs[r * 130 + cw + 1] = v;
        }
        for (int idx = w; idx < 9 * K54; idx += 128)
            ws[(idx / K54) * 56 + idx % K54] = g_Wt[ci * 9 * K54 + idx];
        __syncthreads();

        float xv0[9], xv1[9];
#pragma unroll
        for (int dh = 0; dh < 3; dh++)
#pragma unroll
            for (int dw = 0; dw < 3; dw++) {
                xv0[dh * 3 + dw] = xs[dh * 130 + w + dw];
                xv1[dh * 3 + dw] = xs[(dh + 1) * 130 + w + dw];
            }
#pragma unroll
        for (int tap = 0; tap < 9; tap++) {
            float a0 = xv0[tap], a1 = xv1[tap];
            const float4* wr = (const float4*)&ws[tap * 56];
#pragma unroll
            for (int k4 = 0; k4 < 13; k4++) {
                float4 wv = wr[k4];
                int k = k4 * 4;
                acc0[k + 0] = fmaf(a0, wv.x, acc0[k + 0]);
                acc1[k + 0] = fmaf(a1, wv.x, acc1[k + 0]);
                acc0[k + 1] = fmaf(a0, wv.y, acc0[k + 1]);
                acc1[k + 1] = fmaf(a1, wv.y, acc1[k + 1]);
                acc0[k + 2] = fmaf(a0, wv.z, acc0[k + 2]);
                acc1[k + 2] = fmaf(a1, wv.z, acc1[k + 2]);
                acc0[k + 3] = fmaf(a0, wv.w, acc0[k + 3]);
                acc1[k + 3] = fmaf(a1, wv.w, acc1[k + 3]);
            }
            float w52 = ws[tap * 56 + 52], w53 = ws[tap * 56 + 53];
            acc0[52] = fmaf(a0, w52, acc0[52]);
            acc1[52] = fmaf(a1, w52, acc1[52]);
            acc0[53] = fmaf(a0, w53, acc0[53]);
            acc1[53] = fmaf(a1, w53, acc1[53]);
        }
    }
    float* op0 = g_off + (b * HWD + h0 * WW + w) * K54;
    float* op1 = op0 + WW * K54;
#pragma unroll
    for (int k = 0; k < K54; k++) {
        float sc = (k < 18) ? 1.f : ((k < 36) ? 2.f : 3.f);
        op0[k] = (acc0[k] + bp[k]) * sc;
        op1[k] = (acc1[k] + bp[k]) * sc;
    }
}

// ---------------- k3: gather + bilinear + channel mix + stats ---------------
// block = 256 thr handles 64 pixels of one (s,b,h) half-row.
// Phase A: 8 lanes per pixel, lane = 8 channels (fp16 LDG.128 gathers, fp32 acc).
// Phase B: 64x64 GEMM; thread = (pixel, 16 outputs).
__global__ void __launch_bounds__(256) k_gather(const float* __restrict__ WcG) {
    __shared__ float Wc_sh[64 * 64];      // [c][o]
    __shared__ float xoff[64 * 65];       // [p][c] pitch 65
    __shared__ float off_sh[64 * 19];     // [p][18] pitch 19

    int h = blockIdx.x >> 1;
    int w0 = (blockIdx.x & 1) * 64;
    int b = blockIdx.y, s = blockIdx.z;
    int tid = threadIdx.x;

    for (int idx = tid; idx < 4096; idx += 256) {
        int o = idx >> 6, c = idx & 63;
        Wc_sh[c * 64 + o] = WcG[s * 4096 + idx];   // Wc[o][c] -> [c][o]
    }
    {
        const float* ob = g_off + (size_t)(b * HWD + h * WW + w0) * K54 + s * 18;
        for (int idx = tid; idx < 64 * 18; idx += 256) {
            int p = idx / 18, j = idx % 18;
            off_sh[p * 19 + j] = ob[p * K54 + j];
        }
    }
    __syncthreads();

    const __half* xHb = g_xH + (size_t)b * HWD * CC;
    const float inv9 = 1.f / 9.f;
    int l = tid & 7;                       // channel-octet lane

#pragma unroll
    for (int pass = 0; pass < 2; pass++) {
        int p = pass * 32 + (tid >> 3);
        const float* offp = &off_sh[p * 19];
        float acc[8];
#pragma unroll
        for (int j = 0; j < 8; j++) acc[j] = 0.f;
#pragma unroll
        for (int n = 0; n < 9; n++) {
            float px = (float)(h + n / 3) + offp[n];
            float py = (float)(w0 + p + n % 3) + offp[9 + n];
            float flx = floorf(px), fly = floorf(py);
            float fx = px - flx, fy = py - fly;
            int raw = (int)(flx * 128.f + fly);
            float wlt = (1.f - fx) * (1.f - fy);
            float wrb = fx * fy;
            float wlb = (1.f - fx) * fy;       // corner raw+1
            float wrt = fx * (1.f - fy);       // corner raw+128
            int ilt = min(max(raw, 0), HWD - 1);
            int ilb = min(max(raw + 1, 0), HWD - 1);
            int irt = min(max(raw + 128, 0), HWD - 1);
            int irb = min(max(raw + 129, 0), HWD - 1);
#pragma unroll
            for (int cnr = 0; cnr < 4; cnr++) {
                int gi = (cnr == 0) ? ilt : (cnr == 1) ? irb : (cnr == 2) ? ilb : irt;
                float wgt = (cnr == 0) ? wlt : (cnr == 1) ? wrb : (cnr == 2) ? wlb : wrt;
                uint4 v = *(const uint4*)(xHb + (size_t)gi * CC + l * 8);
                const __half2* hp = (const __half2*)&v;
#pragma unroll
                for (int k = 0; k < 4; k++) {
                    float2 f = __half22float2(hp[k]);
                    acc[2 * k + 0] = fmaf(wgt, f.x, acc[2 * k + 0]);
                    acc[2 * k + 1] = fmaf(wgt, f.y, acc[2 * k + 1]);
                }
            }
        }
#pragma unroll
        for (int j = 0; j < 8; j++) xoff[p * 65 + l * 8 + j] = acc[j] * inv9;
    }
    __syncthreads();

    // Phase B: y[p][o] = sum_c xoff[p][c] * Wc[o][c]
    int p = tid & 63;
    int obase = (tid >> 6) * 16;
    float acc[16];
#pragma unroll
    for (int q = 0; q < 16; q++) acc[q] = 0.f;
    for (int c = 0; c < 64; c++) {
        float xv = xoff[p * 65 + c];
        const float4* w4 = (const float4*)&Wc_sh[c * 64 + obase];
#pragma unroll
        for (int j = 0; j < 4; j++) {
            float4 wv = w4[j];
            acc[4 * j + 0] = fmaf(xv, wv.x, acc[4 * j + 0]);
            acc[4 * j + 1] = fmaf(xv, wv.y, acc[4 * j + 1]);
            acc[4 * j + 2] = fmaf(xv, wv.z, acc[4 * j + 2]);
            acc[4 * j + 3] = fmaf(xv, wv.w, acc[4 * j + 3]);
        }
    }
    float* yb = g_y + ((size_t)(s * BB + b) * CC) * HWD + h * WW + w0;
#pragma unroll
    for (int q = 0; q < 16; q++) yb[(size_t)(obase + q) * HWD + p] = acc[q];

    // BN partial stats: warp-reduce each output channel over this warp's 32 pixels
    int lane = tid & 31;
#pragma unroll
    for (int q = 0; q < 16; q++) {
        float v = acc[q], v2 = v * v;
#pragma unroll
        for (int ofs = 16; ofs > 0; ofs >>= 1) {
            v += __shfl_down_sync(0xffffffffu, v, ofs);
            v2 += __shfl_down_sync(0xffffffffu, v2, ofs);
        }
        if (lane == 0) {
            atomicAdd(&g_sum[s * CC + obase + q], v);
            atomicAdd(&g_sumsq[s * CC + obase + q], v2);
        }
    }
}

// ---------------- k4: finalize BN coefficients ------------------------------
__global__ void k_stats(const float* __restrict__ gamma, const float* __restrict__ beta) {
    int t = threadIdx.x;
    if (t < NS * CC) {
        float inv = 1.f / CNT;
        float mu = g_sum[t] * inv;
        float var = g_sumsq[t] * inv - mu * mu;
        float A = gamma[t] * rsqrtf(var + BN_EPS);
        g_AB[t * 2] = A;
        g_AB[t * 2 + 1] = beta[t] - mu * A;
    }
}

// ---------------- k5: normalize + SiLU + average scales ---------------------
__global__ void k_final(float* __restrict__ out) {
    int idx = blockIdx.x * blockDim.x + threadIdx.x;   // over B*C*HWD
    int o = (idx >> 14) & 63;
    float r = 0.f;
#pragma unroll
    for (int s = 0; s < NS; s++) {
        float v = g_y[(size_t)s * BB * CC * HWD + idx];
        int t = s * CC + o;
        float yn = fmaf(v, g_AB[t * 2], g_AB[t * 2 + 1]);
        r += yn / (1.f + expf(-yn));
    }
    out[idx] = r * (1.f / 3.f);
}

// ---------------- launch ----------------------------------------------------
extern "C" void kernel_launch(void* const* d_in, const int* in_sizes, int n_in,
                              void* d_out, int out_size) {
    const float* x     = (const float*)d_in[0];
    const float* Wp    = (const float*)d_in[1];
    const float* bp    = (const float*)d_in[2];
    const float* Wc    = (const float*)d_in[3];
    const float* gamma = (const float*)d_in[4];
    const float* beta  = (const float*)d_in[5];
    float* out = (float*)d_out;

    dim3 tb(32, 8);
    dim3 tg(HWD / 32, CC / 32, BB);
    k_transpose<<<tg, tb>>>(x);
    k_prep<<<128, 256>>>(Wp);
    k_conv<<<dim3(HH / 2, BB), 128>>>(x, bp);
    k_gather<<<dim3(HH * 2, BB, NS), 256>>>(Wc);
    k_stats<<<1, 256>>>(gamma, beta);
    k_final<<<(BB * CC * HWD) / 256, 256>>>(out);
}

// round 7
// speedup vs baseline: 1.3769x; 1.2929x over previous
#include <cuda_runtime.h>
#include <cuda_fp16.h>
#include <cstdint>
#include <math.h>

#define BB 8
#define CC 64
#define HH 128
#define WW 128
#define HWD 16384
#define NS 3
#define K54 54
#define WSP 56                      // padded weight pitch (floats) per tap
#define CNT 131072.0f
#define BN_EPS 1e-5f

// ---------------- scratch (device globals; no runtime allocation) ----------
__device__ __half g_xH[BB * HWD * CC];         // x as [b][hw][c] fp16 (16.8 MB)
__device__ float g_off[BB * HWD * K54];        // offsets channel-last (28.3 MB)
__device__ float g_Wt[CC * 9 * WSP];           // Wp as [ci][tap][k54 padded to 56]
__device__ float g_y[NS * BB * CC * HWD];      // pre-BN y [s][b][o][hw] (100 MB)
__device__ float g_sum[NS * CC];
__device__ float g_sumsq[NS * CC];
__device__ float g_AB[NS * CC * 2];            // A = gamma*rsqrt(var+eps), B = beta-mu*A

// ---------------- cp.async helpers -----------------------------------------
__device__ __forceinline__ void cpa4(unsigned s, const void* g, bool v) {
    asm volatile("cp.async.ca.shared.global [%0], [%1], 4, %2;"
                 :: "r"(s), "l"(g), "r"(v ? 4u : 0u));
}
__device__ __forceinline__ void cpa16(unsigned s, const void* g) {
    asm volatile("cp.async.cg.shared.global [%0], [%1], 16;" :: "r"(s), "l"(g));
}
__device__ __forceinline__ void cpa_commit() {
    asm volatile("cp.async.commit_group;");
}
template <int N>
__device__ __forceinline__ void cpa_wait() {
    asm volatile("cp.async.wait_group %0;" :: "n"(N));
}

// ---------------- k0: transpose x (b,c,hw) -> (b,hw,c) fp16 ----------------
__global__ void k_transpose(const float* __restrict__ x) {
    __shared__ float t[32][33];                // t[c_local][hw_local]
    int b = blockIdx.z;
    int hw0 = blockIdx.x * 32;
    int c0 = blockIdx.y * 32;
    int tx = threadIdx.x, ty = threadIdx.y;   // (32, 8)
    int tid = ty * 32 + tx;
#pragma unroll
    for (int j = 0; j < 4; j++)
        t[ty + 8 * j][tx] = x[(b * CC + c0 + ty + 8 * j) * HWD + hw0 + tx];
    __syncthreads();
    __half2* outp = (__half2*)g_xH;
#pragma unroll
    for (int idx = tid; idx < 512; idx += 256) {
        int hwl = idx >> 4, cp = idx & 15;
        __half2 v = __floats2half2_rn(t[2 * cp][hwl], t[2 * cp + 1][hwl]);
        outp[((size_t)(b * HWD + hw0 + hwl) * CC + c0) / 2 + cp] = v;
    }
}

// ---------------- k1: transpose Wp (padded) + zero stats --------------------
__global__ void k_prep(const float* __restrict__ Wp) {
    int idx = blockIdx.x * blockDim.x + threadIdx.x;
    if (idx < CC * 9 * WSP) {
        int ci = idx / (9 * WSP);
        int rem = idx % (9 * WSP);
        int tap = rem / WSP;
        int k = rem % WSP;
        g_Wt[idx] = (k < K54) ? Wp[(k * CC + ci) * 9 + tap] : 0.f;
    }
    if (idx < NS * CC) { g_sum[idx] = 0.f; g_sumsq[idx] = 0.f; }
}

// ---------------- k2: 3x3 offset conv, cp.async double-buffered -------------
// block = 128 threads = one output row; 1 pixel/thread, 54 accumulators.
__global__ void __launch_bounds__(128) k_conv(const float* __restrict__ x,
                                              const float* __restrict__ bp) {
    __shared__ float xs[2][3 * 132];   // rows h-1..h+1, padded cols
    __shared__ float ws[2][9 * WSP];   // [tap][k54] pitch 56
    int b = blockIdx.y;
    int h = blockIdx.x;
    int w = threadIdx.x;

    unsigned xs_s[2], ws_s[2];
    xs_s[0] = (unsigned)__cvta_generic_to_shared(&xs[0][0]);
    xs_s[1] = (unsigned)__cvta_generic_to_shared(&xs[1][0]);
    ws_s[0] = (unsigned)__cvta_generic_to_shared(&ws[0][0]);
    ws_s[1] = (unsigned)__cvta_generic_to_shared(&ws[1][0]);

    const float* xb = x + (size_t)b * CC * HWD;

    auto prefetch = [&](int ci, int bi) {
        const float* xc = xb + (size_t)ci * HWD;
#pragma unroll
        for (int it = 0; it < 4; it++) {
            int idx = w + it * 128;
            if (idx < 396) {
                int r = idx / 132, cw = idx % 132 - 1;
                int hh = h - 1 + r;
                bool valid = (hh >= 0) & (hh < HH) & (cw >= 0) & (cw < WW);
                const float* gp = xc + min(max(hh, 0), HH - 1) * WW + min(max(cw, 0), WW - 1);
                cpa4(xs_s[bi] + idx * 4, gp, valid);
            }
        }
        if (w < 126)
            cpa16(ws_s[bi] + w * 16, &g_Wt[ci * 9 * WSP + w * 4]);
    };

    float acc[K54];
#pragma unroll
    for (int k = 0; k < K54; k++) acc[k] = 0.f;

    prefetch(0, 0);
    cpa_commit();

    for (int ci = 0; ci < CC; ci++) {
        int bi = ci & 1;
        __syncthreads();                       // everyone done with buf bi^1 (compute ci-1)
        if (ci + 1 < CC) {
            prefetch(ci + 1, bi ^ 1);
            cpa_commit();
            cpa_wait<1>();
        } else {
            cpa_wait<0>();
        }
        __syncthreads();                       // buf bi data visible to all

        float xv[9];
#pragma unroll
        for (int dh = 0; dh < 3; dh++)
#pragma unroll
            for (int dw = 0; dw < 3; dw++)
                xv[dh * 3 + dw] = xs[bi][dh * 132 + w + dw];
#pragma unroll
        for (int tap = 0; tap < 9; tap++) {
            float a = xv[tap];
            const float4* wr = (const float4*)&ws[bi][tap * WSP];
#pragma unroll
            for (int k4 = 0; k4 < 13; k4++) {
                float4 wv = wr[k4];
                int k = k4 * 4;
                acc[k + 0] = fmaf(a, wv.x, acc[k + 0]);
                acc[k + 1] = fmaf(a, wv.y, acc[k + 1]);
                acc[k + 2] = fmaf(a, wv.z, acc[k + 2]);
                acc[k + 3] = fmaf(a, wv.w, acc[k + 3]);
            }
            acc[52] = fmaf(a, ws[bi][tap * WSP + 52], acc[52]);
            acc[53] = fmaf(a, ws[bi][tap * WSP + 53], acc[53]);
        }
    }
    float* op = g_off + ((size_t)b * HWD + h * WW + w) * K54;
#pragma unroll
    for (int k = 0; k < K54; k++) {
        float sc = (k < 18) ? 1.f : ((k < 36) ? 2.f : 3.f);
        op[k] = (acc[k] + bp[k]) * sc;
    }
}

// ---------------- k3: gather + bilinear + channel mix + stats ---------------
// block = 512 thr, 64 pixels of one (s,b,h) half-row, ONE pass.
// Phase A: 8 lanes per pixel (fp16 LDG.128 gathers, fp32 acc).
// Phase B: thread = (pixel, 8 outputs).
__global__ void __launch_bounds__(512) k_gather(const float* __restrict__ WcG) {
    __shared__ float Wc_sh[64 * 64];      // [c][o]
    __shared__ float xoff[64 * 65];       // [p][c] pitch 65
    __shared__ float off_sh[64 * 19];     // [p][18] pitch 19

    int h = blockIdx.x >> 1;
    int w0 = (blockIdx.x & 1) * 64;
    int b = blockIdx.y, s = blockIdx.z;
    int tid = threadIdx.x;

    for (int idx = tid; idx < 4096; idx += 512) {
        int o = idx >> 6, c = idx & 63;
        Wc_sh[c * 64 + o] = WcG[s * 4096 + idx];   // Wc[o][c] -> [c][o]
    }
    {
        const float* ob = g_off + ((size_t)(b * HWD + h * WW + w0)) * K54 + s * 18;
        for (int idx = tid; idx < 64 * 18; idx += 512) {
            int p = idx / 18, j = idx % 18;
            off_sh[p * 19 + j] = ob[p * K54 + j];
        }
    }
    __syncthreads();

    const __half* xHb = g_xH + (size_t)b * HWD * CC;
    const float inv9 = 1.f / 9.f;
    {
        int p = tid >> 3;                  // 0..63
        int l = tid & 7;                   // channel octet
        const float* offp = &off_sh[p * 19];
        float acc[8];
#pragma unroll
        for (int j = 0; j < 8; j++) acc[j] = 0.f;
#pragma unroll
        for (int n = 0; n < 9; n++) {
            float px = (float)(h + n / 3) + offp[n];
            float py = (float)(w0 + p + n % 3) + offp[9 + n];
            float flx = floorf(px), fly = floorf(py);
            float fx = px - flx, fy = py - fly;
            int raw = (int)(flx * 128.f + fly);
            float wlt = (1.f - fx) * (1.f - fy);
            float wrb = fx * fy;
            float wlb = (1.f - fx) * fy;       // corner raw+1
            float wrt = fx * (1.f - fy);       // corner raw+128
            int i0 = min(max(raw, 0), HWD - 1);
            int i1 = min(max(raw + 1, 0), HWD - 1);
            int i2 = min(max(raw + 128, 0), HWD - 1);
            int i3 = min(max(raw + 129, 0), HWD - 1);
            uint4 v0 = *(const uint4*)(xHb + (size_t)i0 * CC + l * 8);
            uint4 v1 = *(const uint4*)(xHb + (size_t)i1 * CC + l * 8);
            uint4 v2 = *(const uint4*)(xHb + (size_t)i2 * CC + l * 8);
            uint4 v3 = *(const uint4*)(xHb + (size_t)i3 * CC + l * 8);
            const __half2* h0 = (const __half2*)&v0;
            const __half2* h1 = (const __half2*)&v1;
            const __half2* h2 = (const __half2*)&v2;
            const __half2* h3 = (const __half2*)&v3;
#pragma unroll
            for (int k = 0; k < 4; k++) {
                float2 f0 = __half22float2(h0[k]);
                float2 f1 = __half22float2(h1[k]);
                float2 f2 = __half22float2(h2[k]);
                float2 f3 = __half22float2(h3[k]);
                acc[2 * k + 0] = fmaf(wlt, f0.x, acc[2 * k + 0]);
                acc[2 * k + 1] = fmaf(wlt, f0.y, acc[2 * k + 1]);
                acc[2 * k + 0] = fmaf(wlb, f1.x, acc[2 * k + 0]);
                acc[2 * k + 1] = fmaf(wlb, f1.y, acc[2 * k + 1]);
                acc[2 * k + 0] = fmaf(wrt, f2.x, acc[2 * k + 0]);
                acc[2 * k + 1] = fmaf(wrt, f2.y, acc[2 * k + 1]);
                acc[2 * k + 0] = fmaf(wrb, f3.x, acc[2 * k + 0]);
                acc[2 * k + 1] = fmaf(wrb, f3.y, acc[2 * k + 1]);
            }
        }
#pragma unroll
        for (int j = 0; j < 8; j++) xoff[p * 65 + l * 8 + j] = acc[j] * inv9;
    }
    __syncthreads();

    // Phase B: y[p][o] = sum_c xoff[p][c] * Wc[o][c], 8 outs/thread
    int p = tid & 63;
    int obase = (tid >> 6) * 8;
    float acc[8];
#pragma unroll
    for (int q = 0; q < 8; q++) acc[q] = 0.f;
    for (int c = 0; c < 64; c++) {
        float xv = xoff[p * 65 + c];
        const float4* w4 = (const float4*)&Wc_sh[c * 64 + obase];
        float4 wa = w4[0], wb = w4[1];
        acc[0] = fmaf(xv, wa.x, acc[0]);
        acc[1] = fmaf(xv, wa.y, acc[1]);
        acc[2] = fmaf(xv, wa.z, acc[2]);
        acc[3] = fmaf(xv, wa.w, acc[3]);
        acc[4] = fmaf(xv, wb.x, acc[4]);
        acc[5] = fmaf(xv, wb.y, acc[5]);
        acc[6] = fmaf(xv, wb.z, acc[6]);
        acc[7] = fmaf(xv, wb.w, acc[7]);
    }
    float* yb = g_y + ((size_t)(s * BB + b) * CC) * HWD + h * WW + w0;
#pragma unroll
    for (int q = 0; q < 8; q++) yb[(size_t)(obase + q) * HWD + p] = acc[q];

    // BN partial stats: within a warp all lanes share obase, distinct p
    int lane = tid & 31;
#pragma unroll
    for (int q = 0; q < 8; q++) {
        float v = acc[q], v2 = v * v;
#pragma unroll
        for (int ofs = 16; ofs > 0; ofs >>= 1) {
            v += __shfl_down_sync(0xffffffffu, v, ofs);
            v2 += __shfl_down_sync(0xffffffffu, v2, ofs);
        }
        if (lane == 0) {
            atomicAdd(&g_sum[s * CC + obase + q], v);
            atomicAdd(&g_sumsq[s * CC + obase + q], v2);
        }
    }
}

// ---------------- k4: finalize BN coefficients ------------------------------
__global__ void k_stats(const float* __restrict__ gamma, const float* __restrict__ beta) {
    int t = threadIdx.x;
    if (t < NS * CC) {
        float inv = 1.f / CNT;
        float mu = g_sum[t] * inv;
        float var = g_sumsq[t] * inv - mu * mu;
        float A = gamma[t] * rsqrtf(var + BN_EPS);
        g_AB[t * 2] = A;
        g_AB[t * 2 + 1] = beta[t] - mu * A;
    }
}

// ---------------- k5: normalize + SiLU + average scales ---------------------
__global__ void k_final(float* __restrict__ out) {
    int idx = blockIdx.x * blockDim.x + threadIdx.x;   // over B*C*HWD
    int o = (idx >> 14) & 63;
    float r = 0.f;
#pragma unroll
    for (int s = 0; s < NS; s++) {
        float v = g_y[(size_t)s * BB * CC * HWD + idx];
        int t = s * CC + o;
        float yn = fmaf(v, g_AB[t * 2], g_AB[t * 2 + 1]);
        r += yn / (1.f + expf(-yn));
    }
    out[idx] = r * (1.f / 3.f);
}

// ---------------- launch ----------------------------------------------------
extern "C" void kernel_launch(void* const* d_in, const int* in_sizes, int n_in,
                              void* d_out, int out_size) {
    const float* x     = (const float*)d_in[0];
    const float* Wp    = (const float*)d_in[1];
    const float* bp    = (const float*)d_in[2];
    const float* Wc    = (const float*)d_in[3];
    const float* gamma = (const float*)d_in[4];
    const float* beta  = (const float*)d_in[5];
    float* out = (float*)d_out;

    dim3 tb(32, 8);
    dim3 tg(HWD / 32, CC / 32, BB);
    k_transpose<<<tg, tb>>>(x);
    k_prep<<<((CC * 9 * WSP) + 255) / 256, 256>>>(Wp);
    k_conv<<<dim3(HH, BB), 128>>>(x, bp);
    k_gather<<<dim3(HH * 2, BB, NS), 512>>>(Wc);
    k_stats<<<1, 256>>>(gamma, beta);
    k_final<<<(BB * CC * HWD) / 256, 256>>>(out);
}